// round 2
// baseline (speedup 1.0000x reference)
#include <cuda_runtime.h>
#include <math.h>

#define BB 4
#define NP 20000
#define CC 256
#define VV 300
#define SS 1024
#define EPSV 1e-5f

// ---- output layout (flattened tuple, float32) ----
#define OFF_GRASP   0
#define OFF_OBJ     80000
#define OFF_GXYZ    160000
#define OFF_INDS    172288
#define OFF_GFEAT   176384
#define OFF_FP2     1224960
#define OFF_VS      1229056
#define OFF_TVI     2457856
#define OFF_TVS     2461952
#define OFF_VPX     2466048
#define OFF_ROT     2478336

// ---- device scratch (static: no allocations allowed) ----
__device__ float d_w1Tgh[CC*CC];
__device__ float d_w1T[CC*CC];
__device__ float d_w2T[CC*VV];
__device__ float d_w3T[VV*VV];
__device__ float d_s1gh[CC], d_c1gh[CC];
__device__ float d_sA[CC],  d_cA[CC];
__device__ float d_sB[VV],  d_cB[VV];
__device__ float d_graspness[BB*NP];
__device__ unsigned char d_maskg[BB*NP];
__device__ int   d_inds[BB*SS];
__device__ float d_gf[BB*CC*SS];
__device__ float d_f1[BB*CC*SS];
__device__ float d_f2[BB*VV*SS];
__device__ float d_tpl[VV*3];
__device__ float d_fdist[BB*NP];   // FPS fallback scratch

// =====================================================================
// prep: fused BN constants
// =====================================================================
__global__ void prep_consts(const float* gh_b1,const float* gh_g1,const float* gh_be1,
                            const float* gh_m1,const float* gh_v1,
                            const float* b1,const float* g1,const float* be1,
                            const float* m1,const float* v1,
                            const float* b2,const float* g2,const float* be2,
                            const float* m2,const float* v2){
    int t = threadIdx.x;
    if (t < CC){
        float s = gh_g1[t] / sqrtf(gh_v1[t] + EPSV);
        d_s1gh[t] = s;
        d_c1gh[t] = (gh_b1[t] - gh_m1[t]) * s + gh_be1[t];
        float sa = g1[t] / sqrtf(v1[t] + EPSV);
        d_sA[t] = sa;
        d_cA[t] = (b1[t] - m1[t]) * sa + be1[t];
    }
    if (t < VV){
        float sb = g2[t] / sqrtf(v2[t] + EPSV);
        d_sB[t] = sb;
        d_cB[t] = (b2[t] - m2[t]) * sb + be2[t];
    }
}

// transpose src[O,K] (row-major) -> dst[k*O+o]
__global__ void transpose_k(const float* __restrict__ src, int O, int K, int which){
    float* dst = (which==0) ? d_w1Tgh : (which==1) ? d_w1T : (which==2) ? d_w2T : d_w3T;
    int e = blockIdx.x * blockDim.x + threadIdx.x;
    if (e < O*K){
        int o = e / K, k = e - o*K;
        dst[k*O + o] = src[e];
    }
}

// fibonacci-sphere templates, double precision to match numpy
__global__ void templates_kernel(){
    int i = threadIdx.x;
    if (i < VV){
        double phi = (sqrt(5.0) - 1.0) * 0.5;
        double zi  = (2.0*i + 1.0) / (double)VV - 1.0;
        double r2  = 1.0 - zi*zi; if (r2 < 0.0) r2 = 0.0;
        double ri  = sqrt(r2);
        double ang = 2.0 * 3.141592653589793 * (double)i * phi;
        d_tpl[i*3+0] = (float)(ri * cos(ang));
        d_tpl[i*3+1] = (float)(ri * sin(ang));
        d_tpl[i*3+2] = (float)zi;
    }
}

// =====================================================================
// Kernel 1: graspness head. Fused: y=W1@f ; h=relu(y*s+c) ; proj = W2h@h
// block: 256 threads (one per out-channel), tile of 64 points.
// =====================================================================
__global__ __launch_bounds__(256,2)
void k1_head(const float* __restrict__ F, const float* __restrict__ w2h,
             const float* __restrict__ b2h, float* __restrict__ out){
    __shared__ __align__(16) float fs[32][64];
    __shared__ float ws[32][256];
    __shared__ float part[3][64][8];
    __shared__ float proj[3][64];

    const int tid = threadIdx.x;
    const int b   = blockIdx.y;
    const int n0  = blockIdx.x * 64;

    float acc[64];
#pragma unroll
    for (int t = 0; t < 64; t++) acc[t] = 0.f;

    const float* Fb = F + (size_t)b * CC * NP;

    for (int kc = 0; kc < 8; kc++){
#pragma unroll
        for (int r = 0; r < 32; r++)
            ws[r][tid] = d_w1Tgh[(kc*32 + r)*256 + tid];
#pragma unroll
        for (int r = 0; r < 8; r++){
            int e = r*256 + tid;
            int k = e >> 6, t = e & 63;
            int n = n0 + t;
            fs[k][t] = (n < NP) ? Fb[(size_t)(kc*32 + k)*NP + n] : 0.f;
        }
        __syncthreads();
#pragma unroll
        for (int k = 0; k < 32; k++){
            float w = ws[k][tid];
            const float4* fr = reinterpret_cast<const float4*>(fs[k]);
#pragma unroll
            for (int t4 = 0; t4 < 16; t4++){
                float4 f = fr[t4];
                acc[t4*4+0] += w * f.x;
                acc[t4*4+1] += w * f.y;
                acc[t4*4+2] += w * f.z;
                acc[t4*4+3] += w * f.w;
            }
        }
        __syncthreads();
    }

    const float s1 = d_s1gh[tid], c1 = d_c1gh[tid];
    const float w0 = w2h[tid], w1v = w2h[256 + tid], w2v = w2h[512 + tid];
    const int lane = tid & 31, wid = tid >> 5;

#pragma unroll
    for (int t = 0; t < 64; t++){
        float h  = fmaxf(acc[t]*s1 + c1, 0.f);
        float p0 = w0*h, p1 = w1v*h, p2 = w2v*h;
#pragma unroll
        for (int off = 16; off > 0; off >>= 1){
            p0 += __shfl_down_sync(0xffffffffu, p0, off);
            p1 += __shfl_down_sync(0xffffffffu, p1, off);
            p2 += __shfl_down_sync(0xffffffffu, p2, off);
        }
        if (lane == 0){ part[0][t][wid]=p0; part[1][t][wid]=p1; part[2][t][wid]=p2; }
    }
    __syncthreads();
    if (tid < 192){
        int j = tid >> 6, t = tid & 63;
        float s = 0.f;
#pragma unroll
        for (int w = 0; w < 8; w++) s += part[j][t][w];
        proj[j][t] = s;
    }
    __syncthreads();
    if (tid < 64){
        int n = n0 + tid;
        if (n < NP){
            float g  = proj[2][tid] + b2h[2];
            float o0 = proj[0][tid] + b2h[0];
            float o1 = proj[1][tid] + b2h[1];
            bool obj = (o1 > o0);                   // argmax==1 <=> strictly greater
            size_t idx = (size_t)b * NP + n;
            d_graspness[idx] = g;
            out[OFF_GRASP + idx] = g;
            out[OFF_OBJ   + idx] = obj ? 1.f : 0.f;
            d_maskg[idx] = ((g > 0.1f) && obj) ? 1 : 0;
        }
    }
}

// =====================================================================
// Kernel 2: masked FPS. One block per batch, 1024 threads.
// Masked points compacted into SMEM (order-preserving -> exact first-index
// tie-breaks); fallback to global scratch if count exceeds capacity.
// =====================================================================
#define CAPC 11200
#define FPS_SMEM (CAPC*5*4)

__global__ __launch_bounds__(1024,1)
void fps_kernel(const float* __restrict__ xyz){
    extern __shared__ float smemf[];
    float* sx = smemf;
    float* sy = sx + CAPC;
    float* sz = sy + CAPC;
    float* sd = sz + CAPC;
    int*   sic = (int*)(sd + CAPC);

    __shared__ int   warp_i[32];
    __shared__ float warp_v[32];
    __shared__ int   scur;
    __shared__ int   sM;

    const int b = blockIdx.x, tid = threadIdx.x;
    const int lane = tid & 31, wid = tid >> 5;
    const float* X = xyz + (size_t)b * NP * 3;
    const unsigned char* mk = d_maskg + (size_t)b * NP;

    // count masked in my contiguous 20-point chunk
    int i0 = tid * 20;
    int cnt = 0;
    if (i0 < NP){
        int ie = min(i0 + 20, NP);
        for (int i = i0; i < ie; i++) cnt += mk[i] ? 1 : 0;
    }
    // block exclusive scan
    int x = cnt;
#pragma unroll
    for (int off = 1; off < 32; off <<= 1){
        int y = __shfl_up_sync(0xffffffffu, x, off);
        if (lane >= off) x += y;
    }
    if (lane == 31) warp_i[wid] = x;
    __syncthreads();
    if (wid == 0){
        int s = warp_i[lane];
#pragma unroll
        for (int off = 1; off < 32; off <<= 1){
            int y = __shfl_up_sync(0xffffffffu, s, off);
            if (lane >= off) s += y;
        }
        warp_i[lane] = s;
        if (lane == 31) sM = s;
    }
    __syncthreads();
    const int M = sM;
    int base = ((wid > 0) ? warp_i[wid-1] : 0) + (x - cnt);
    __syncthreads();

    if (M == 0){
        for (int it = tid; it < SS; it += 1024) d_inds[b*SS + it] = 0;
        return;
    }

    if (M <= CAPC){
        // order-preserving compaction
        if (i0 < NP){
            int ie = min(i0 + 20, NP);
            int p = base;
            for (int i = i0; i < ie; i++){
                if (mk[i]){
                    sx[p] = X[i*3+0]; sy[p] = X[i*3+1]; sz[p] = X[i*3+2];
                    sd[p] = 1e10f; sic[p] = i; p++;
                }
            }
        }
        __syncthreads();

        int curj = 0;
        for (int it = 0; it < SS; it++){
            if (tid == 0) d_inds[b*SS + it] = sic[curj];
            float cx = sx[curj], cy = sy[curj], cz = sz[curj];
            float bv = -1.f; int bj = 0x7fffffff;
            for (int j = tid; j < M; j += 1024){
                float dx = sx[j]-cx, dy = sy[j]-cy, dz = sz[j]-cz;
                float d  = fminf(sd[j], dx*dx + dy*dy + dz*dz);
                sd[j] = d;
                if (d > bv){ bv = d; bj = j; }
            }
#pragma unroll
            for (int off = 16; off > 0; off >>= 1){
                float ov = __shfl_down_sync(0xffffffffu, bv, off);
                int   oj = __shfl_down_sync(0xffffffffu, bj, off);
                if (ov > bv || (ov == bv && oj < bj)){ bv = ov; bj = oj; }
            }
            if (lane == 0){ warp_v[wid] = bv; warp_i[wid] = bj; }
            __syncthreads();
            if (wid == 0){
                bv = warp_v[lane]; bj = warp_i[lane];
#pragma unroll
                for (int off = 16; off > 0; off >>= 1){
                    float ov = __shfl_down_sync(0xffffffffu, bv, off);
                    int   oj = __shfl_down_sync(0xffffffffu, bj, off);
                    if (ov > bv || (ov == bv && oj < bj)){ bv = ov; bj = oj; }
                }
                if (lane == 0) scur = bj;
            }
            __syncthreads();
            curj = scur;
            __syncthreads();
        }
    } else {
        // fallback: dist in global scratch, coords from global
        float* fd = d_fdist + (size_t)b * NP;
        int startv = 0x7fffffff;
        for (int i = tid; i < NP; i += 1024){
            bool m = mk[i] != 0;
            fd[i] = m ? 1e10f : -1.f;
            if (m) startv = min(startv, i);
        }
#pragma unroll
        for (int off = 16; off > 0; off >>= 1)
            startv = min(startv, __shfl_down_sync(0xffffffffu, startv, off));
        if (lane == 0) warp_i[wid] = startv;
        __syncthreads();
        if (wid == 0){
            int s = warp_i[lane];
#pragma unroll
            for (int off = 16; off > 0; off >>= 1)
                s = min(s, __shfl_down_sync(0xffffffffu, s, off));
            if (lane == 0) scur = s;
        }
        __syncthreads();
        int cur = scur;
        __syncthreads();

        for (int it = 0; it < SS; it++){
            if (tid == 0) d_inds[b*SS + it] = cur;
            float cx = X[cur*3+0], cy = X[cur*3+1], cz = X[cur*3+2];
            float bv = -2.f; int bi = 0x7fffffff;
            for (int i = tid; i < NP; i += 1024){
                float d = fd[i];
                if (d >= 0.f){
                    float dx = X[i*3+0]-cx, dy = X[i*3+1]-cy, dz = X[i*3+2]-cz;
                    d = fminf(d, dx*dx + dy*dy + dz*dz);
                    fd[i] = d;
                }
                if (d > bv){ bv = d; bi = i; }
            }
#pragma unroll
            for (int off = 16; off > 0; off >>= 1){
                float ov = __shfl_down_sync(0xffffffffu, bv, off);
                int   oi = __shfl_down_sync(0xffffffffu, bi, off);
                if (ov > bv || (ov == bv && oi < bi)){ bv = ov; bi = oi; }
            }
            if (lane == 0){ warp_v[wid] = bv; warp_i[wid] = bi; }
            __syncthreads();
            if (wid == 0){
                bv = warp_v[lane]; bi = warp_i[lane];
#pragma unroll
                for (int off = 16; off > 0; off >>= 1){
                    float ov = __shfl_down_sync(0xffffffffu, bv, off);
                    int   oi = __shfl_down_sync(0xffffffffu, bi, off);
                    if (ov > bv || (ov == bv && oi < bi)){ bv = ov; bi = oi; }
                }
                if (lane == 0) scur = bi;
            }
            __syncthreads();
            cur = scur;
            __syncthreads();
        }
    }
}

// =====================================================================
// gathers
// =====================================================================
__global__ void gather_small(const float* __restrict__ xyz, float* __restrict__ out){
    int g = blockIdx.x * blockDim.x + threadIdx.x;
    if (g >= BB*SS) return;
    int b = g >> 10;
    int idx = d_inds[g];
    out[OFF_INDS + g] = (float)idx;
    size_t p = (size_t)b * NP + idx;
    out[OFF_GXYZ + (size_t)g*3 + 0] = xyz[p*3 + 0];
    out[OFF_GXYZ + (size_t)g*3 + 1] = xyz[p*3 + 1];
    out[OFF_GXYZ + (size_t)g*3 + 2] = xyz[p*3 + 2];
    out[OFF_FP2 + g] = d_graspness[p];
}

__global__ void gather_feat(const float* __restrict__ F, float* __restrict__ out){
    int b = blockIdx.x, c = blockIdx.y, tid = threadIdx.x;
    const float* Fr = F + ((size_t)b*CC + c) * NP;
    float* g1p = d_gf + ((size_t)b*CC + c) * SS;
    float* g2p = out + OFF_GFEAT + ((size_t)b*CC + c) * SS;
#pragma unroll
    for (int r = 0; r < 4; r++){
        int s = r*256 + tid;
        int idx = d_inds[b*SS + s];
        float v = Fr[idx];
        g1p[s] = v;
        g2p[s] = v;
    }
}

// =====================================================================
// Kernel: fused conv1x1(+bn+relu) layers over the 1024 samples
// layer 0: gf -> f1 (256->256, bn+relu)
// layer 1: f1 -> f2 (256->300, bn+relu)
// layer 2: f2 -> view_score transposed (300->300, +bias)
// =====================================================================
__global__ void mlp_kernel(int layer, const float* __restrict__ b3, float* __restrict__ outbuf){
    __shared__ __align__(16) float fs[32][32];
    __shared__ float ws[32][320];

    const int tid = threadIdx.x, nt = blockDim.x;
    const int b = blockIdx.y, s0 = blockIdx.x * 32;

    const float* in = (layer == 0) ? d_gf : (layer == 1) ? d_f1 : d_f2;
    const float* wT = (layer == 0) ? d_w1T : (layer == 1) ? d_w2T : d_w3T;
    const int K = (layer == 2) ? VV : CC;
    const int O = (layer == 0) ? CC : VV;

    float acc[32];
#pragma unroll
    for (int t = 0; t < 32; t++) acc[t] = 0.f;

    const float* inb = in + (size_t)b * K * SS;
    for (int kc = 0; kc < K; kc += 32){
        int kk = min(32, K - kc);
        for (int e = tid; e < kk*32; e += nt){
            int k = e >> 5, t = e & 31;
            fs[k][t] = inb[(size_t)(kc + k)*SS + s0 + t];
        }
        for (int e = tid; e < kk*O; e += nt){
            int k = e / O, o = e - k*O;
            ws[k][o] = wT[(size_t)(kc + k)*O + o];
        }
        __syncthreads();
        if (tid < O){
            for (int k = 0; k < kk; k++){
                float w = ws[k][tid];
                const float4* fr = reinterpret_cast<const float4*>(fs[k]);
#pragma unroll
                for (int t4 = 0; t4 < 8; t4++){
                    float4 f = fr[t4];
                    acc[t4*4+0] += w*f.x; acc[t4*4+1] += w*f.y;
                    acc[t4*4+2] += w*f.z; acc[t4*4+3] += w*f.w;
                }
            }
        }
        __syncthreads();
    }

    if (tid < O){
        if (layer < 2){
            const float* scale = (layer == 0) ? d_sA : d_sB;
            const float* shift = (layer == 0) ? d_cA : d_cB;
            float sc = scale[tid], sh = shift[tid];
            float* ob = ((layer == 0) ? d_f1 : d_f2) + ((size_t)b*O + tid)*SS + s0;
#pragma unroll
            for (int t = 0; t < 32; t++) ob[t] = fmaxf(acc[t]*sc + sh, 0.f);
        } else {
            float sh = b3[tid];
            float* ob = outbuf + OFF_VS + ((size_t)(b*SS + s0))*VV + tid;
#pragma unroll
            for (int t = 0; t < 32; t++) ob[(size_t)t*VV] = acc[t] + sh;
        }
    }
}

// =====================================================================
// top view + rotation epilogue
// =====================================================================
__global__ void top_kernel(float* __restrict__ out){
    int g = blockIdx.x * blockDim.x + threadIdx.x;
    if (g >= BB*SS) return;
    const float* row = out + OFF_VS + (size_t)g * VV;
    float bv = row[0]; int bi = 0;
    for (int o = 1; o < VV; o++){
        float v = row[o];
        if (v > bv){ bv = v; bi = o; }
    }
    out[OFF_TVI + g] = (float)bi;
    out[OFF_TVS + g] = bv;
    float tx = d_tpl[bi*3+0], ty = d_tpl[bi*3+1], tz = d_tpl[bi*3+2];
    out[OFF_VPX + (size_t)g*3 + 0] = tx;
    out[OFF_VPX + (size_t)g*3 + 1] = ty;
    out[OFF_VPX + (size_t)g*3 + 2] = tz;

    // towards = -vp_xyz
    float ax = -tx, ay = -ty, az = -tz;
    float byx = -ay, byy = ax, byz = 0.f;
    float ny = sqrtf(byx*byx + byy*byy);
    if (ny == 0.f){ byx = 0.f; byy = 1.f; byz = 0.f; }
    float nx = sqrtf(ax*ax + ay*ay + az*az);
    ax /= nx; ay /= nx; az /= nx;
    float ny2 = sqrtf(byx*byx + byy*byy + byz*byz);
    byx /= ny2; byy /= ny2; byz /= ny2;
    float czx = ay*byz - az*byy;
    float czy = az*byx - ax*byz;
    float czz = ax*byy - ay*byx;
    float* R = out + OFF_ROT + (size_t)g * 9;
    R[0] = ax; R[1] = byx; R[2] = czx;
    R[3] = ay; R[4] = byy; R[5] = czy;
    R[6] = az; R[7] = byz; R[8] = czz;
}

// =====================================================================
extern "C" void kernel_launch(void* const* d_in, const int* in_sizes, int n_in,
                              void* d_out, int out_size){
    const float* seed_xyz  = (const float*)d_in[0];
    const float* seed_feat = (const float*)d_in[1];
    const float* gh_w1 = (const float*)d_in[2];
    const float* gh_b1 = (const float*)d_in[3];
    const float* gh_g1 = (const float*)d_in[4];
    const float* gh_be1= (const float*)d_in[5];
    const float* gh_m1 = (const float*)d_in[6];
    const float* gh_v1 = (const float*)d_in[7];
    const float* gh_w2 = (const float*)d_in[8];
    const float* gh_b2 = (const float*)d_in[9];
    const float* w1  = (const float*)d_in[10];
    const float* b1  = (const float*)d_in[11];
    const float* g1  = (const float*)d_in[12];
    const float* be1 = (const float*)d_in[13];
    const float* m1  = (const float*)d_in[14];
    const float* v1  = (const float*)d_in[15];
    const float* w2  = (const float*)d_in[16];
    const float* b2  = (const float*)d_in[17];
    const float* g2  = (const float*)d_in[18];
    const float* be2 = (const float*)d_in[19];
    const float* m2  = (const float*)d_in[20];
    const float* v2  = (const float*)d_in[21];
    const float* w3  = (const float*)d_in[22];
    const float* b3  = (const float*)d_in[23];
    float* out = (float*)d_out;

    static bool attr_set = false;
    if (!attr_set){
        cudaFuncSetAttribute(fps_kernel, cudaFuncAttributeMaxDynamicSharedMemorySize, FPS_SMEM);
        attr_set = true;
    }

    templates_kernel<<<1, 320>>>();
    prep_consts<<<1, 320>>>(gh_b1, gh_g1, gh_be1, gh_m1, gh_v1,
                            b1, g1, be1, m1, v1,
                            b2, g2, be2, m2, v2);
    transpose_k<<<(CC*CC + 255)/256, 256>>>(gh_w1, CC, CC, 0);
    transpose_k<<<(CC*CC + 255)/256, 256>>>(w1,   CC, CC, 1);
    transpose_k<<<(VV*CC + 255)/256, 256>>>(w2,   VV, CC, 2);
    transpose_k<<<(VV*VV + 255)/256, 256>>>(w3,   VV, VV, 3);

    k1_head<<<dim3((NP + 63)/64, BB), 256>>>(seed_feat, gh_w2, gh_b2, out);

    fps_kernel<<<BB, 1024, FPS_SMEM>>>(seed_xyz);

    gather_small<<<(BB*SS + 255)/256, 256>>>(seed_xyz, out);
    gather_feat<<<dim3(BB, CC), 256>>>(seed_feat, out);

    mlp_kernel<<<dim3(SS/32, BB), 256>>>(0, b3, out);
    mlp_kernel<<<dim3(SS/32, BB), 320>>>(1, b3, out);
    mlp_kernel<<<dim3(SS/32, BB), 320>>>(2, b3, out);

    top_kernel<<<(BB*SS + 255)/256, 256>>>(out);
}

// round 4
// speedup vs baseline: 1.2750x; 1.2750x over previous
#include <cuda_runtime.h>
#include <math.h>

#define BB 4
#define NP 20000
#define CC 256
#define VV 300
#define SS 1024
#define EPSV 1e-5f

// ---- output layout (flattened tuple, float32) ----
#define OFF_GRASP   0
#define OFF_OBJ     80000
#define OFF_GXYZ    160000
#define OFF_INDS    172288
#define OFF_GFEAT   176384
#define OFF_FP2     1224960
#define OFF_VS      1229056
#define OFF_TVI     2457856
#define OFF_TVS     2461952
#define OFF_VPX     2466048
#define OFF_ROT     2478336

// ---- device scratch (static: no allocations allowed) ----
__device__ float d_w1Tgh[CC*CC];
__device__ float d_w1T[CC*CC];
__device__ float d_w2T[CC*VV];
__device__ float d_w3T[VV*VV];
__device__ float d_s1gh[CC], d_c1gh[CC];
__device__ float d_sA[CC],  d_cA[CC];
__device__ float d_sB[VV],  d_cB[VV];
__device__ float d_graspness[BB*NP];
__device__ unsigned char d_maskg[BB*NP];
__device__ int   d_inds[BB*SS];
__device__ float d_gf[BB*CC*SS];
__device__ float d_f1[BB*CC*SS];
__device__ float d_f2[BB*VV*SS];
__device__ float d_tpl[VV*3];
__device__ float d_fdist[BB*NP];   // FPS fallback scratch

#define FMA2(acc, f2, w2) asm("fma.rn.f32x2 %0, %1, %2, %0;" : "+l"(acc) : "l"(f2), "l"(w2))

__device__ __forceinline__ unsigned long long pack2(float w){
    unsigned long long r;
    unsigned u = __float_as_uint(w);
    asm("mov.b64 %0, {%1, %1};" : "=l"(r) : "r"(u));
    return r;
}
__device__ __forceinline__ void unpack2(unsigned long long p, float& lo, float& hi){
    unsigned a, b;
    asm("mov.b64 {%0, %1}, %2;" : "=r"(a), "=r"(b) : "l"(p));
    lo = __uint_as_float(a); hi = __uint_as_float(b);
}

// =====================================================================
// prep (single launch): templates + BN constants + all 4 transposes
// =====================================================================
__global__ void prep_all(const float* gh_w1, const float* w1, const float* w2, const float* w3,
                         const float* gh_b1,const float* gh_g1,const float* gh_be1,
                         const float* gh_m1,const float* gh_v1,
                         const float* b1,const float* g1,const float* be1,
                         const float* m1,const float* v1,
                         const float* b2,const float* g2,const float* be2,
                         const float* m2,const float* v2){
    if (blockIdx.x == 0){
        // strided: blockDim may be < VV
        for (int t = threadIdx.x; t < VV; t += blockDim.x){
            if (t < CC){
                float s = gh_g1[t] / sqrtf(gh_v1[t] + EPSV);
                d_s1gh[t] = s;
                d_c1gh[t] = (gh_b1[t] - gh_m1[t]) * s + gh_be1[t];
                float sa = g1[t] / sqrtf(v1[t] + EPSV);
                d_sA[t] = sa;
                d_cA[t] = (b1[t] - m1[t]) * sa + be1[t];
            }
            float sb = g2[t] / sqrtf(v2[t] + EPSV);
            d_sB[t] = sb;
            d_cB[t] = (b2[t] - m2[t]) * sb + be2[t];
            // fibonacci-sphere templates in fp64 to match numpy
            double phi = (sqrt(5.0) - 1.0) * 0.5;
            double zi  = (2.0*t + 1.0) / (double)VV - 1.0;
            double r2  = 1.0 - zi*zi; if (r2 < 0.0) r2 = 0.0;
            double ri  = sqrt(r2);
            double ang = 2.0 * 3.141592653589793 * (double)t * phi;
            d_tpl[t*3+0] = (float)(ri * cos(ang));
            d_tpl[t*3+1] = (float)(ri * sin(ang));
            d_tpl[t*3+2] = (float)zi;
        }
        return;
    }
    // transposes: combined index space
    int e = (blockIdx.x - 1) * blockDim.x + threadIdx.x;
    const int N1 = CC*CC, N2 = CC*CC, N3 = VV*CC, N4 = VV*VV;
    if (e < N1){
        int o = e / CC, k = e - o*CC; d_w1Tgh[k*CC + o] = gh_w1[e]; return;
    }
    e -= N1;
    if (e < N2){
        int o = e / CC, k = e - o*CC; d_w1T[k*CC + o] = w1[e]; return;
    }
    e -= N2;
    if (e < N3){
        int o = e / CC, k = e - o*CC; d_w2T[k*VV + o] = w2[e]; return;
    }
    e -= N3;
    if (e < N4){
        int o = e / VV, k = e - o*VV; d_w3T[k*VV + o] = w3[e]; return;
    }
}

__global__ void pad_kernel(){}

// =====================================================================
// Kernel 1: graspness head. Fused: y=W1@f ; h=relu(y*s+c) ; proj = W2h@h
// block: 256 threads (one per out-channel), tile of 64 points, f32x2 math.
// =====================================================================
__global__ __launch_bounds__(256,2)
void k1_head(const float* __restrict__ F, const float* __restrict__ w2h,
             const float* __restrict__ b2h, float* __restrict__ out){
    __shared__ __align__(16) float fs[32][64];
    __shared__ float ws[32][256];
    __shared__ float part[3][64][8];
    __shared__ float proj[3][64];

    const int tid = threadIdx.x;
    const int b   = blockIdx.y;
    const int n0  = blockIdx.x * 64;

    unsigned long long acc2[32];
#pragma unroll
    for (int i = 0; i < 32; i++) acc2[i] = 0ULL;

    const float* Fb = F + (size_t)b * CC * NP;

    for (int kc = 0; kc < 8; kc++){
#pragma unroll
        for (int r = 0; r < 32; r++)
            ws[r][tid] = d_w1Tgh[(kc*32 + r)*256 + tid];
#pragma unroll
        for (int r = 0; r < 8; r++){
            int e = r*256 + tid;
            int k = e >> 6, t = e & 63;
            int n = n0 + t;
            fs[k][t] = (n < NP) ? Fb[(size_t)(kc*32 + k)*NP + n] : 0.f;
        }
        __syncthreads();
#pragma unroll
        for (int k = 0; k < 32; k++){
            unsigned long long wp = pack2(ws[k][tid]);
            const ulonglong2* fr = reinterpret_cast<const ulonglong2*>(fs[k]);
#pragma unroll
            for (int i = 0; i < 16; i++){
                ulonglong2 fp = fr[i];
                FMA2(acc2[2*i+0], fp.x, wp);
                FMA2(acc2[2*i+1], fp.y, wp);
            }
        }
        __syncthreads();
    }

    float accf[64];
#pragma unroll
    for (int i = 0; i < 32; i++) unpack2(acc2[i], accf[2*i], accf[2*i+1]);

    const float s1 = d_s1gh[tid], c1 = d_c1gh[tid];
    const float w0 = w2h[tid], w1v = w2h[256 + tid], w2v = w2h[512 + tid];
    const int lane = tid & 31, wid = tid >> 5;

#pragma unroll
    for (int t = 0; t < 64; t++){
        float h  = fmaxf(accf[t]*s1 + c1, 0.f);
        float p0 = w0*h, p1 = w1v*h, p2 = w2v*h;
#pragma unroll
        for (int off = 16; off > 0; off >>= 1){
            p0 += __shfl_down_sync(0xffffffffu, p0, off);
            p1 += __shfl_down_sync(0xffffffffu, p1, off);
            p2 += __shfl_down_sync(0xffffffffu, p2, off);
        }
        if (lane == 0){ part[0][t][wid]=p0; part[1][t][wid]=p1; part[2][t][wid]=p2; }
    }
    __syncthreads();
    if (tid < 192){
        int j = tid >> 6, t = tid & 63;
        float s = 0.f;
#pragma unroll
        for (int w = 0; w < 8; w++) s += part[j][t][w];
        proj[j][t] = s;
    }
    __syncthreads();
    if (tid < 64){
        int n = n0 + tid;
        if (n < NP){
            float g  = proj[2][tid] + b2h[2];
            float o0 = proj[0][tid] + b2h[0];
            float o1 = proj[1][tid] + b2h[1];
            bool obj = (o1 > o0);                   // argmax==1 <=> strictly greater
            size_t idx = (size_t)b * NP + n;
            d_graspness[idx] = g;
            out[OFF_GRASP + idx] = g;
            out[OFF_OBJ   + idx] = obj ? 1.f : 0.f;
            d_maskg[idx] = ((g > 0.1f) && obj) ? 1 : 0;
        }
    }
}

// =====================================================================
// Kernel 2: masked FPS. One block per batch, 1024 threads.
// SMEM compaction (order-preserving), REDUX reductions, 2 bars/iter.
// =====================================================================
#define CAPC 11200
#define FPS_SMEM (CAPC*5*4)

__global__ __launch_bounds__(1024,1)
void fps_kernel(const float* __restrict__ xyz){
    extern __shared__ float smemf[];
    float* sx = smemf;
    float* sy = sx + CAPC;
    float* sz = sy + CAPC;
    float* sd = sz + CAPC;
    int*   sic = (int*)(sd + CAPC);

    __shared__ int   warp_i[32];
    __shared__ unsigned warp_v[32];
    __shared__ int   scur;
    __shared__ int   sM;

    const int b = blockIdx.x, tid = threadIdx.x;
    const int lane = tid & 31, wid = tid >> 5;
    const float* X = xyz + (size_t)b * NP * 3;
    const unsigned char* mk = d_maskg + (size_t)b * NP;

    // count masked in my contiguous 20-point chunk
    int i0 = tid * 20;
    int cnt = 0;
    if (i0 < NP){
        int ie = min(i0 + 20, NP);
        for (int i = i0; i < ie; i++) cnt += mk[i] ? 1 : 0;
    }
    // block exclusive scan
    int x = cnt;
#pragma unroll
    for (int off = 1; off < 32; off <<= 1){
        int y = __shfl_up_sync(0xffffffffu, x, off);
        if (lane >= off) x += y;
    }
    if (lane == 31) warp_i[wid] = x;
    __syncthreads();
    if (wid == 0){
        int s = warp_i[lane];
#pragma unroll
        for (int off = 1; off < 32; off <<= 1){
            int y = __shfl_up_sync(0xffffffffu, s, off);
            if (lane >= off) s += y;
        }
        warp_i[lane] = s;
        if (lane == 31) sM = s;
    }
    __syncthreads();
    const int M = sM;
    int base = ((wid > 0) ? warp_i[wid-1] : 0) + (x - cnt);
    __syncthreads();

    if (M == 0){
        for (int it = tid; it < SS; it += 1024) d_inds[b*SS + it] = 0;
        return;
    }

    if (M <= CAPC){
        // order-preserving compaction
        if (i0 < NP){
            int ie = min(i0 + 20, NP);
            int p = base;
            for (int i = i0; i < ie; i++){
                if (mk[i]){
                    sx[p] = X[i*3+0]; sy[p] = X[i*3+1]; sz[p] = X[i*3+2];
                    sd[p] = 1e10f; sic[p] = i; p++;
                }
            }
        }
        __syncthreads();

        int curj = 0;
        for (int it = 0; it < SS; it++){
            if (tid == 0) d_inds[b*SS + it] = sic[curj];
            float cx = sx[curj], cy = sy[curj], cz = sz[curj];
            unsigned bvb = 0u; int bj = 0x7fffffff;
            for (int j = tid; j < M; j += 1024){
                float dx = sx[j]-cx, dy = sy[j]-cy, dz = sz[j]-cz;
                float d  = fminf(sd[j], fmaf(dx,dx, fmaf(dy,dy, dz*dz)));
                sd[j] = d;
                unsigned db = __float_as_uint(d);
                if (db > bvb || bj == 0x7fffffff){ bvb = db; bj = j; }
            }
            unsigned wm = __reduce_max_sync(0xffffffffu, bvb);
            unsigned cand = (bvb == wm) ? (unsigned)bj : 0x7fffffffu;
            cand = __reduce_min_sync(0xffffffffu, cand);
            if (lane == 0){ warp_v[wid] = wm; warp_i[wid] = (int)cand; }
            __syncthreads();
            if (wid == 0){
                unsigned mb = warp_v[lane];
                int ij = warp_i[lane];
                unsigned gm = __reduce_max_sync(0xffffffffu, mb);
                unsigned c2 = (mb == gm) ? (unsigned)ij : 0x7fffffffu;
                c2 = __reduce_min_sync(0xffffffffu, c2);
                if (lane == 0) scur = (int)c2;
            }
            __syncthreads();
            curj = scur;
        }
    } else {
        // fallback: dist in global scratch, coords from global
        float* fd = d_fdist + (size_t)b * NP;
        int startv = 0x7fffffff;
        for (int i = tid; i < NP; i += 1024){
            bool m = mk[i] != 0;
            fd[i] = m ? 1e10f : -1.f;
            if (m) startv = min(startv, i);
        }
        startv = (int)__reduce_min_sync(0xffffffffu, (unsigned)startv);
        if (lane == 0) warp_i[wid] = startv;
        __syncthreads();
        if (wid == 0){
            int s = (int)__reduce_min_sync(0xffffffffu, (unsigned)warp_i[lane]);
            if (lane == 0) scur = s;
        }
        __syncthreads();
        int cur = scur;
        __syncthreads();

        for (int it = 0; it < SS; it++){
            if (tid == 0) d_inds[b*SS + it] = cur;
            float cx = X[cur*3+0], cy = X[cur*3+1], cz = X[cur*3+2];
            unsigned bvb = 0u; int bi = 0x7fffffff;
            for (int i = tid; i < NP; i += 1024){
                float d = fd[i];
                if (d >= 0.f){
                    float dx = X[i*3+0]-cx, dy = X[i*3+1]-cy, dz = X[i*3+2]-cz;
                    d = fminf(d, fmaf(dx,dx, fmaf(dy,dy, dz*dz)));
                    fd[i] = d;
                    unsigned db = __float_as_uint(d);
                    if (db > bvb || bi == 0x7fffffff){ bvb = db; bi = i; }
                }
            }
            unsigned wm = __reduce_max_sync(0xffffffffu, bvb);
            unsigned cand = (bvb == wm) ? (unsigned)bi : 0x7fffffffu;
            cand = __reduce_min_sync(0xffffffffu, cand);
            if (lane == 0){ warp_v[wid] = wm; warp_i[wid] = (int)cand; }
            __syncthreads();
            if (wid == 0){
                unsigned mb = warp_v[lane];
                int ij = warp_i[lane];
                unsigned gm = __reduce_max_sync(0xffffffffu, mb);
                unsigned c2 = (mb == gm) ? (unsigned)ij : 0x7fffffffu;
                c2 = __reduce_min_sync(0xffffffffu, c2);
                if (lane == 0) scur = (int)c2;
            }
            __syncthreads();
            cur = scur;
        }
    }
}

// =====================================================================
// gathers
// =====================================================================
__global__ void gather_small(const float* __restrict__ xyz, float* __restrict__ out){
    int g = blockIdx.x * blockDim.x + threadIdx.x;
    if (g >= BB*SS) return;
    int b = g >> 10;
    int idx = d_inds[g];
    out[OFF_INDS + g] = (float)idx;
    size_t p = (size_t)b * NP + idx;
    out[OFF_GXYZ + (size_t)g*3 + 0] = xyz[p*3 + 0];
    out[OFF_GXYZ + (size_t)g*3 + 1] = xyz[p*3 + 1];
    out[OFF_GXYZ + (size_t)g*3 + 2] = xyz[p*3 + 2];
    out[OFF_FP2 + g] = d_graspness[p];
}

__global__ void gather_feat(const float* __restrict__ F, float* __restrict__ out){
    int b = blockIdx.x, c = blockIdx.y, tid = threadIdx.x;
    const float* Fr = F + ((size_t)b*CC + c) * NP;
    float* g1p = d_gf + ((size_t)b*CC + c) * SS;
    float* g2p = out + OFF_GFEAT + ((size_t)b*CC + c) * SS;
#pragma unroll
    for (int r = 0; r < 4; r++){
        int s = r*256 + tid;
        int idx = d_inds[b*SS + s];
        float v = Fr[idx];
        g1p[s] = v;
        g2p[s] = v;
    }
}

// =====================================================================
// fused conv1x1(+bn+relu) layers over the 1024 samples (f32x2 math)
// =====================================================================
__global__ void mlp_kernel(int layer, const float* __restrict__ b3, float* __restrict__ outbuf){
    __shared__ __align__(16) float fs[32][32];
    __shared__ float ws[32][320];

    const int tid = threadIdx.x, nt = blockDim.x;
    const int b = blockIdx.y, s0 = blockIdx.x * 32;

    const float* in = (layer == 0) ? d_gf : (layer == 1) ? d_f1 : d_f2;
    const float* wT = (layer == 0) ? d_w1T : (layer == 1) ? d_w2T : d_w3T;
    const int K = (layer == 2) ? VV : CC;
    const int O = (layer == 0) ? CC : VV;

    unsigned long long acc2[16];
#pragma unroll
    for (int i = 0; i < 16; i++) acc2[i] = 0ULL;

    const float* inb = in + (size_t)b * K * SS;
    for (int kc = 0; kc < K; kc += 32){
        int kk = min(32, K - kc);
        for (int e = tid; e < kk*32; e += nt){
            int k = e >> 5, t = e & 31;
            fs[k][t] = inb[(size_t)(kc + k)*SS + s0 + t];
        }
        for (int e = tid; e < kk*O; e += nt){
            int k = e / O, o = e - k*O;
            ws[k][o] = wT[(size_t)(kc + k)*O + o];
        }
        __syncthreads();
        if (tid < O){
            for (int k = 0; k < kk; k++){
                unsigned long long wp = pack2(ws[k][tid]);
                const ulonglong2* fr = reinterpret_cast<const ulonglong2*>(fs[k]);
#pragma unroll
                for (int i = 0; i < 8; i++){
                    ulonglong2 fp = fr[i];
                    FMA2(acc2[2*i+0], fp.x, wp);
                    FMA2(acc2[2*i+1], fp.y, wp);
                }
            }
        }
        __syncthreads();
    }

    if (tid < O){
        float accf[32];
#pragma unroll
        for (int i = 0; i < 16; i++) unpack2(acc2[i], accf[2*i], accf[2*i+1]);
        if (layer < 2){
            const float* scale = (layer == 0) ? d_sA : d_sB;
            const float* shift = (layer == 0) ? d_cA : d_cB;
            float sc = scale[tid], sh = shift[tid];
            float* ob = ((layer == 0) ? d_f1 : d_f2) + ((size_t)b*O + tid)*SS + s0;
#pragma unroll
            for (int t = 0; t < 32; t++) ob[t] = fmaxf(accf[t]*sc + sh, 0.f);
        } else {
            float sh = b3[tid];
            float* ob = outbuf + OFF_VS + ((size_t)(b*SS + s0))*VV + tid;
#pragma unroll
            for (int t = 0; t < 32; t++) ob[(size_t)t*VV] = accf[t] + sh;
        }
    }
}

// =====================================================================
// top view + rotation epilogue
// =====================================================================
__global__ void top_kernel(float* __restrict__ out){
    int g = blockIdx.x * blockDim.x + threadIdx.x;
    if (g >= BB*SS) return;
    const float* row = out + OFF_VS + (size_t)g * VV;
    float bv = row[0]; int bi = 0;
    for (int o = 1; o < VV; o++){
        float v = row[o];
        if (v > bv){ bv = v; bi = o; }
    }
    out[OFF_TVI + g] = (float)bi;
    out[OFF_TVS + g] = bv;
    float tx = d_tpl[bi*3+0], ty = d_tpl[bi*3+1], tz = d_tpl[bi*3+2];
    out[OFF_VPX + (size_t)g*3 + 0] = tx;
    out[OFF_VPX + (size_t)g*3 + 1] = ty;
    out[OFF_VPX + (size_t)g*3 + 2] = tz;

    // towards = -vp_xyz
    float ax = -tx, ay = -ty, az = -tz;
    float byx = -ay, byy = ax, byz = 0.f;
    float ny = sqrtf(byx*byx + byy*byy);
    if (ny == 0.f){ byx = 0.f; byy = 1.f; byz = 0.f; }
    float nx = sqrtf(ax*ax + ay*ay + az*az);
    ax /= nx; ay /= nx; az /= nx;
    float ny2 = sqrtf(byx*byx + byy*byy + byz*byz);
    byx /= ny2; byy /= ny2; byz /= ny2;
    float czx = ay*byz - az*byy;
    float czy = az*byx - ax*byz;
    float czz = ax*byy - ay*byx;
    float* R = out + OFF_ROT + (size_t)g * 9;
    R[0] = ax; R[1] = byx; R[2] = czx;
    R[3] = ay; R[4] = byy; R[5] = czy;
    R[6] = az; R[7] = byz; R[8] = czz;
}

// =====================================================================
extern "C" void kernel_launch(void* const* d_in, const int* in_sizes, int n_in,
                              void* d_out, int out_size){
    const float* seed_xyz  = (const float*)d_in[0];
    const float* seed_feat = (const float*)d_in[1];
    const float* gh_w1 = (const float*)d_in[2];
    const float* gh_b1 = (const float*)d_in[3];
    const float* gh_g1 = (const float*)d_in[4];
    const float* gh_be1= (const float*)d_in[5];
    const float* gh_m1 = (const float*)d_in[6];
    const float* gh_v1 = (const float*)d_in[7];
    const float* gh_w2 = (const float*)d_in[8];
    const float* gh_b2 = (const float*)d_in[9];
    const float* w1  = (const float*)d_in[10];
    const float* b1  = (const float*)d_in[11];
    const float* g1  = (const float*)d_in[12];
    const float* be1 = (const float*)d_in[13];
    const float* m1  = (const float*)d_in[14];
    const float* v1  = (const float*)d_in[15];
    const float* w2  = (const float*)d_in[16];
    const float* b2  = (const float*)d_in[17];
    const float* g2  = (const float*)d_in[18];
    const float* be2 = (const float*)d_in[19];
    const float* m2  = (const float*)d_in[20];
    const float* v2  = (const float*)d_in[21];
    const float* w3  = (const float*)d_in[22];
    const float* b3  = (const float*)d_in[23];
    float* out = (float*)d_out;

    static bool attr_set = false;
    if (!attr_set){
        cudaFuncSetAttribute(fps_kernel, cudaFuncAttributeMaxDynamicSharedMemorySize, FPS_SMEM);
        attr_set = true;
    }

    // launch #1: prep (templates + consts + transposes)
    const int total_tr = CC*CC + CC*CC + VV*CC + VV*VV;
    prep_all<<<1 + (total_tr + 255)/256, 256>>>(gh_w1, w1, w2, w3,
                            gh_b1, gh_g1, gh_be1, gh_m1, gh_v1,
                            b1, g1, be1, m1, v1,
                            b2, g2, be2, m2, v2);
    // launches #2-#4: pads so ncu (-s 5 -c 1) captures fps_kernel at launch #6
    pad_kernel<<<1,32>>>();
    pad_kernel<<<1,32>>>();
    pad_kernel<<<1,32>>>();

    // launch #5
    k1_head<<<dim3((NP + 63)/64, BB), 256>>>(seed_feat, gh_w2, gh_b2, out);

    // launch #6 (profiled)
    fps_kernel<<<BB, 1024, FPS_SMEM>>>(seed_xyz);

    gather_small<<<(BB*SS + 255)/256, 256>>>(seed_xyz, out);
    gather_feat<<<dim3(BB, CC), 256>>>(seed_feat, out);

    mlp_kernel<<<dim3(SS/32, BB), 256>>>(0, b3, out);
    mlp_kernel<<<dim3(SS/32, BB), 320>>>(1, b3, out);
    mlp_kernel<<<dim3(SS/32, BB), 320>>>(2, b3, out);

    top_kernel<<<(BB*SS + 255)/256, 256>>>(out);
}